// round 13
// baseline (speedup 1.0000x reference)
#include <cuda_runtime.h>
#include <math.h>

#define NN 8192
#define RT 8                       // rows per group (fits register budget!)
#define NGROUPS (NN / RT)          // 1024
#define PHASES 8
#define NUNITS ((NGROUPS / 2) * PHASES)   // 512 pairs * 8 phases = 4096
#define BLOCK 512
#define WPB 16
#define GRID 296
#define NLGW ((GRID - 1) * WPB)    // 4720 worker warps (block 295 does ranks)
#define NCHUNK (NN / 128)          // 64 chunks of 128 j's
#define NBINS 4096
#define NPAIRS 33550336.0          // N*(N-1)/2
#define SMEM_BYTES 65536           // e[] (32KB) | rank scratch (64KB)

__device__ double2 g_part[GRID];
__device__ int     g_done = 0;

__device__ __forceinline__ unsigned key_of(float t) {
    unsigned k = __float_as_uint(t);
    return (k & 0x80000000u) ? ~k : (k | 0x80000000u);  // monotone float->uint
}

__global__ void __launch_bounds__(BLOCK, 2)
rrl_kernel(const float* __restrict__ pred, const float* __restrict__ target,
           float* __restrict__ out) {
    extern __shared__ char smem[];
    const int tid  = threadIdx.x;
    const int warp = tid >> 5, lane = tid & 31;
    const int b    = blockIdx.x;

    float acc_l2 = 0.0f;   // sum log2(e_i+e_j)   (blocks 0..294)
    float acc_ps = 0.0f;   // sum p_k * rank_k    (block 295)

    if (b < GRID - 1) {
        // ---------- log-sum blocks: only e[] needed ----------
        float* s_e = (float*)smem;
        for (int i = tid; i < NN; i += BLOCK) s_e[i] = __expf(pred[i]);
        __syncthreads();

        const int W  = b * WPB + warp;
        const int lo = (int)((long long)W * NUNITS / NLGW);
        const int hi = (int)((long long)(W + 1) * NUNITS / NLGW);
        if (hi > lo) {                       // this warp owns unit `lo`
            const int pairid = lo / PHASES;
            const int phase  = lo % PHASES;
            #pragma unroll 1
            for (int sgrp = 0; sgrp < 2; ++sgrp) {
                const int g     = sgrp ? (NGROUPS - 1 - pairid) : pairid;
                const int rbase = g * RT;
                float er[RT];
                #pragma unroll
                for (int r = 0; r < RT; ++r) er[r] = s_e[rbase + r];
                const int c0 = rbase >> 7;           // chunk holding the triangle
                int c = c0 + ((phase - c0) & (PHASES - 1));
                #pragma unroll 1
                for (; c < NCHUNK; c += PHASES) {
                    const int jb = (c << 7) + 4 * lane;
                    const float4 e4 = *(const float4*)(s_e + jb);
                    if (c != c0) {
                        // clean chunk: all 8 rows valid for every j
                        #pragma unroll
                        for (int q = 0; q < 4; ++q) {
                            const float ej = (q == 0) ? e4.x : (q == 1) ? e4.y
                                           : (q == 2) ? e4.z : e4.w;
                            float m0 = (er[0] + ej) * (er[1] + ej);
                            float m1 = (er[2] + ej) * (er[3] + ej);
                            float m2 = (er[4] + ej) * (er[5] + ej);
                            float m3 = (er[6] + ej) * (er[7] + ej);
                            acc_l2 += __log2f((m0 * m1) * (m2 * m3));
                        }
                    } else {
                        // triangle chunk: invalid pairs contribute se=1 (log2=0)
                        #pragma unroll
                        for (int q = 0; q < 4; ++q) {
                            const int   j  = jb + q;
                            const float ej = (q == 0) ? e4.x : (q == 1) ? e4.y
                                           : (q == 2) ? e4.z : e4.w;
                            float se[RT];
                            #pragma unroll
                            for (int r = 0; r < RT; ++r)
                                se[r] = (j > rbase + r) ? (er[r] + ej) : 1.0f;
                            acc_l2 += __log2f(((se[0]*se[1])*(se[2]*se[3]))
                                            * ((se[4]*se[5])*(se[6]*se[7])));
                        }
                    }
                }
            }
        }
    } else {
        // ---------- rank block: sum_ps = sum p_k * #{t_j < t_k} ----------
        unsigned* skey = (unsigned*)smem;                       // [NN]
        unsigned* offs = (unsigned*)(smem + NN * 4);            // [NBINS]
        unsigned* cnts = (unsigned*)(smem + NN * 4 + NBINS * 4);// [NBINS]

        for (int i = tid; i < NBINS; i += BLOCK) cnts[i] = 0;
        __syncthreads();
        for (int k = tid; k < NN; k += BLOCK)
            atomicAdd(&cnts[key_of(target[k]) >> 20], 1u);
        __syncthreads();
        // exclusive prefix sum over 4096 bins (8 per thread, 512 threads)
        {
            unsigned v[8], s = 0;
            #pragma unroll
            for (int q = 0; q < 8; ++q) { v[q] = cnts[8*tid + q]; s += v[q]; }
            const unsigned ts = s;
            #pragma unroll
            for (int o = 1; o < 32; o <<= 1) {
                unsigned n = __shfl_up_sync(0xffffffffu, s, o);
                if (lane >= o) s += n;
            }
            __shared__ unsigned wtot[WPB];
            if (lane == 31) wtot[warp] = s;
            __syncthreads();
            if (warp == 0 && lane < WPB) {
                unsigned x = wtot[lane];
                #pragma unroll
                for (int o = 1; o < WPB; o <<= 1) {
                    unsigned n = __shfl_up_sync(0xffffu, x, o);
                    if (lane >= o) x += n;
                }
                wtot[lane] = x;
            }
            __syncthreads();
            unsigned run = (warp ? wtot[warp - 1] : 0u) + (s - ts);
            #pragma unroll
            for (int q = 0; q < 8; ++q) { offs[8*tid + q] = run; run += v[q]; }
        }
        __syncthreads();
        for (int i = tid; i < NBINS; i += BLOCK) cnts[i] = 0;
        __syncthreads();
        for (int k = tid; k < NN; k += BLOCK) {
            unsigned key = key_of(target[k]);
            unsigned bn  = key >> 20;
            unsigned pos = offs[bn] + atomicAdd(&cnts[bn], 1u);
            skey[pos] = key;
        }
        __syncthreads();
        // rank = elements in smaller bins + strictly-smaller within own bin.
        // Order-invariant w.r.t. scatter order -> deterministic.
        for (int k = tid; k < NN; k += BLOCK) {
            const unsigned key = key_of(target[k]);
            const unsigned bn  = key >> 20;
            const unsigned lo2 = offs[bn], n = cnts[bn];
            unsigned r = lo2;
            for (unsigned s2 = lo2; s2 < lo2 + n; ++s2)
                r += (skey[s2] < key) ? 1u : 0u;
            acc_ps += pred[k] * (float)r;
        }
    }

    // ---------- block reduction ----------
    #pragma unroll
    for (int o = 16; o; o >>= 1) {
        acc_l2 += __shfl_xor_sync(0xffffffffu, acc_l2, o);
        acc_ps += __shfl_xor_sync(0xffffffffu, acc_ps, o);
    }
    __shared__ float rl[WPB], rp[WPB];
    if (lane == 0) { rl[warp] = acc_l2; rp[warp] = acc_ps; }
    __syncthreads();
    if (warp == 0) {
        float a = (lane < WPB) ? rl[lane] : 0.0f;
        float p = (lane < WPB) ? rp[lane] : 0.0f;
        #pragma unroll
        for (int o = 16; o; o >>= 1) {
            a += __shfl_xor_sync(0xffffffffu, a, o);
            p += __shfl_xor_sync(0xffffffffu, p, o);
        }
        if (lane == 0) g_part[b] = make_double2((double)a, (double)p);
    }

    // ---------- last-block final combine ----------
    __threadfence();
    __shared__ int s_last;
    if (tid == 0) s_last = (atomicAdd(&g_done, 1) == GRID - 1) ? 1 : 0;
    __syncthreads();
    if (s_last) {
        double A = 0.0, P = 0.0;
        if (tid < GRID) { double2 v = g_part[tid]; A = v.x; P = v.y; }
        #pragma unroll
        for (int o = 16; o; o >>= 1) {
            A += __shfl_down_sync(0xffffffffu, A, o);
            P += __shfl_down_sync(0xffffffffu, P, o);
        }
        __shared__ double fa[WPB], fp[WPB];
        if (lane == 0) { fa[warp] = A; fp[warp] = P; }
        __syncthreads();
        if (tid == 0) {
            double AA = 0.0, PP = 0.0;
            #pragma unroll
            for (int w = 0; w < WPB; ++w) { AA += fa[w]; PP += fp[w]; }
            const double LN2 = 0.6931471805599453;
            out[0] = (float)((LN2 * AA - PP) / NPAIRS);
            g_done = 0;   // reset for next graph replay
        }
    }
}

extern "C" void kernel_launch(void* const* d_in, const int* in_sizes, int n_in,
                              void* d_out, int out_size) {
    const float* pred   = (const float*)d_in[0];
    const float* target = (const float*)d_in[1];
    float* out = (float*)d_out;
    (void)in_sizes; (void)n_in; (void)out_size;

    cudaFuncSetAttribute(rrl_kernel,
                         cudaFuncAttributeMaxDynamicSharedMemorySize, SMEM_BYTES);

    rrl_kernel<<<GRID, BLOCK, SMEM_BYTES>>>(pred, target, out);
}